// round 4
// baseline (speedup 1.0000x reference)
#include <cuda_runtime.h>
#include <cstdint>

// Problem constants
#define SEQ    512
#define BATCH  64
#define INDIM  128
#define HDIM   512

// Cluster tiling: cluster of 8 CTAs = one batch group of 4 batches.
// CTA rank r owns j-slice [r*64, r*64+64). 16 clusters x 8 = 128 CTAs.
#define CLUSTER 8
#define JT      64                 // j columns per CTA
#define BPC     4                  // batches per cluster
#define NGRP    (BATCH / BPC)      // 16 clusters
#define NCTA    (CLUSTER * NGRP)   // 128
#define THREADS 256
#define NWARP   8

// K-split across warps (float4 chunks)
#define WI_CPW  (INDIM / 4 / NWARP)   // 4
#define WH_CPW  (HDIM / 4 / NWARP)    // 16

// smem layout (float offsets)
#define OFF_WH  0
#define N_WH    (JT * HDIM)          // 32768 (128 KB)
#define OFF_WI  (OFF_WH + N_WH)
#define N_WI    (JT * INDIM)         // 8192  (32 KB)
#define OFF_H   (OFF_WI + N_WI)
#define N_H     (2 * BPC * HDIM)     // 4096  (16 KB, double buffered)
#define OFF_X   (OFF_H + N_H)
#define N_X     (BPC * INDIM)        // 512   (2 KB)
#define OFF_RED (OFF_X + N_X)
#define RED_STRIDE 33                // odd-ish stride -> conflict-free columns
#define N_RED   (JT * RED_STRIDE)    // 2112
#define SMEM_FLOATS (OFF_RED + N_RED)
#define SMEM_BYTES  (SMEM_FLOATS * 4)

// Packed dual-FMA: acc.{lo,hi} += a.{lo,hi} * b.{lo,hi}
#define FMA2(acc, a, b) \
    asm("fma.rn.f32x2 %0, %1, %2, %0;" : "+l"(acc) : "l"(a), "l"(b))

__device__ __forceinline__ uint32_t smem_u32(const void* p) {
    uint32_t a;
    asm("{ .reg .u64 t; cvta.to.shared.u64 t, %1; cvt.u32.u64 %0, t; }"
        : "=r"(a) : "l"(p));
    return a;
}

// Store one float into peer CTA's smem (DSMEM push)
__device__ __forceinline__ void st_cluster_f32(uint32_t laddr, int rank, float v) {
    uint32_t raddr;
    asm volatile("mapa.shared::cluster.u32 %0, %1, %2;"
                 : "=r"(raddr) : "r"(laddr), "r"(rank));
    asm volatile("st.shared::cluster.f32 [%0], %1;" :: "r"(raddr), "f"(v) : "memory");
}

__device__ __forceinline__ void cluster_sync() {
    asm volatile("barrier.cluster.arrive.aligned;" ::: "memory");  // release
    asm volatile("barrier.cluster.wait.aligned;"   ::: "memory");  // acquire
}

__global__ __launch_bounds__(THREADS, 1) __cluster_dims__(CLUSTER, 1, 1)
void rnn_cluster_kernel(const float* __restrict__ x,
                        const float* __restrict__ Wi,
                        const float* __restrict__ bi,
                        const float* __restrict__ Wh,
                        const float* __restrict__ bh,
                        float* __restrict__ out)
{
    extern __shared__ float smem[];
    const int tid  = threadIdx.x;
    const int bx   = blockIdx.x;
    const int grp  = bx >> 3;            // batch group (cluster id)
    const int rank = bx & 7;             // cluster rank = j-slice owner
    const int j0   = rank * JT;
    const int b0   = grp * BPC;
    const int lane = tid & 31;
    const int w    = tid >> 5;           // warp = K-slice owner

    // ---- One-time weight staging, packed [kc][jh][lane][4] for conflict-free LDS.128
    for (int idx = tid; idx < JT * HDIM; idx += THREADS) {
        int jj = idx >> 9;               // 0..63
        int k  = idx & (HDIM - 1);
        smem[OFF_WH + (((k >> 2) * 2 + (jj >> 5)) * 32 + (jj & 31)) * 4 + (k & 3)]
            = Wh[(j0 + jj) * HDIM + k];
    }
    for (int idx = tid; idx < JT * INDIM; idx += THREADS) {
        int jj = idx >> 7;               // 0..63
        int k  = idx & (INDIM - 1);
        smem[OFF_WI + (((k >> 2) * 2 + (jj >> 5)) * 32 + (jj & 31)) * 4 + (k & 3)]
            = Wi[(j0 + jj) * INDIM + k];
    }
    const int   jl = tid & 63;           // final-ownership j within tile
    const int   bo = tid >> 6;           // final-ownership batch within group
    const float cb = bi[j0 + jl] + bh[j0 + jl];

    const ulonglong2* sWh2 = (const ulonglong2*)(smem + OFF_WH);
    const ulonglong2* sWi2 = (const ulonglong2*)(smem + OFF_WI);
    const ulonglong2* sx2  = (const ulonglong2*)(smem + OFF_X);
    float* sred = smem + OFF_RED;

    // smem byte address of this thread's h-slot (buffer-relative), for DSMEM push
    const uint32_t h_base_u32 = smem_u32(smem + OFF_H);

    // Prefetch x[0] tile (4 rows x 128 = 128 float4)
    float4 xr = make_float4(0.f, 0.f, 0.f, 0.f);
    if (tid < 128)
        xr = ((const float4*)(x + (size_t)0 * BATCH * INDIM + b0 * INDIM))[tid];

    __syncthreads();   // weights staged (cluster CTAs independent here)

    for (int t = 0; t < SEQ; t++) {
        const int cur  = t & 1;
        const int prev = cur ^ 1;

        // Stage x[t] from prefetch regs
        if (tid < 128) ((float4*)(smem + OFF_X))[tid] = xr;
        __syncthreads();

        // ---- Partial dot products: warp covers K-slice, all (2 j-halves x 4 batches)
        unsigned long long acc[2][BPC];
        #pragma unroll
        for (int jh = 0; jh < 2; jh++)
            #pragma unroll
            for (int b = 0; b < BPC; b++) acc[jh][b] = 0ull;

        {   // Wi part
            const int c0 = w * WI_CPW;
            #pragma unroll
            for (int c = 0; c < WI_CPW; c++) {
                const int kc = c0 + c;
                ulonglong2 wv0 = sWi2[(kc * 2 + 0) * 32 + lane];
                ulonglong2 wv1 = sWi2[(kc * 2 + 1) * 32 + lane];
                #pragma unroll
                for (int b = 0; b < BPC; b++) {
                    ulonglong2 hv = sx2[b * (INDIM / 4) + kc];   // broadcast
                    FMA2(acc[0][b], wv0.x, hv.x); FMA2(acc[0][b], wv0.y, hv.y);
                    FMA2(acc[1][b], wv1.x, hv.x); FMA2(acc[1][b], wv1.y, hv.y);
                }
            }
        }
        if (t > 0) {  // Wh part, h[t-1] from local smem buffer
            const ulonglong2* sh2 = (const ulonglong2*)(smem + OFF_H + prev * BPC * HDIM);
            const int c0 = w * WH_CPW;
            #pragma unroll 4
            for (int c = 0; c < WH_CPW; c++) {
                const int kc = c0 + c;
                ulonglong2 wv0 = sWh2[(kc * 2 + 0) * 32 + lane];
                ulonglong2 wv1 = sWh2[(kc * 2 + 1) * 32 + lane];
                #pragma unroll
                for (int b = 0; b < BPC; b++) {
                    ulonglong2 hv = sh2[b * (HDIM / 4) + kc];    // broadcast
                    FMA2(acc[0][b], wv0.x, hv.x); FMA2(acc[0][b], wv0.y, hv.y);
                    FMA2(acc[1][b], wv1.x, hv.x); FMA2(acc[1][b], wv1.y, hv.y);
                }
            }
        }

        // Spill partials: sred[j][b*8+w], j = jh*32+lane (stride 33 -> conflict-free)
        #pragma unroll
        for (int jh = 0; jh < 2; jh++)
            #pragma unroll
            for (int b = 0; b < BPC; b++) {
                union { unsigned long long u; float2 f; } c; c.u = acc[jh][b];
                sred[(jh * 32 + lane) * RED_STRIDE + b * NWARP + w] = c.f.x + c.f.y;
            }
        __syncthreads();

        // Prefetch x[t+1] while reduce/exchange/barrier hide the latency
        if (tid < 128 && t + 1 < SEQ)
            xr = ((const float4*)(x + (size_t)(t + 1) * BATCH * INDIM + b0 * INDIM))[tid];

        // ---- Reduce 8 warp-partials, tanh, publish
        {
            const float* r = &sred[jl * RED_STRIDE + bo * NWARP];
            float s = ((r[0] + r[1]) + (r[2] + r[3])) + ((r[4] + r[5]) + (r[6] + r[7]));
            const float val = tanhf(cb + s);

            // global output (no fence needed; consumed only after kernel end)
            out[(size_t)t * BATCH * HDIM + (b0 + bo) * HDIM + j0 + jl] = val;
            if (t == SEQ - 1)
                out[(size_t)SEQ * BATCH * HDIM + (b0 + bo) * HDIM + j0 + jl] = val;

            // DSMEM push into all 8 cluster CTAs' h buffer (buf 'cur')
            const uint32_t slot = h_base_u32 +
                (uint32_t)(((cur * BPC + bo) * HDIM + j0 + jl) * 4);
            #pragma unroll
            for (int pr = 0; pr < CLUSTER; pr++)
                st_cluster_f32(slot, pr, val);
        }

        // One cluster barrier per step: orders DSMEM pushes (release/acquire),
        // doubles as the CTA-wide barrier guarding smem buffer reuse.
        cluster_sync();
    }
}

extern "C" void kernel_launch(void* const* d_in, const int* in_sizes, int n_in,
                              void* d_out, int out_size)
{
    const float* x  = (const float*)d_in[0];
    const float* Wi = (const float*)d_in[1];
    const float* bi = (const float*)d_in[2];
    const float* Wh = (const float*)d_in[3];
    const float* bh = (const float*)d_in[4];
    float* out = (float*)d_out;

    (void)in_sizes; (void)n_in; (void)out_size;

    cudaFuncSetAttribute(rnn_cluster_kernel,
                         cudaFuncAttributeMaxDynamicSharedMemorySize, SMEM_BYTES);
    rnn_cluster_kernel<<<NCTA, THREADS, SMEM_BYTES>>>(x, Wi, bi, Wh, bh, out);
}